// round 14
// baseline (speedup 1.0000x reference)
#include <cuda_runtime.h>
#include <cuda_fp16.h>

namespace {
constexpr int N_COLS = 8192;
constexpr int W_MAX  = 15;     // widths w = 2..15
constexpr int NW     = 14;
constexpr int HALO   = 14;     // W_MAX - 1
constexpr int TPB    = 128;    // 4 warps
constexpr int K_TOK  = 16;     // tokens per lane PER SEGMENT
constexpr int WTOK   = 32 * K_TOK;          // 512 tokens/warp/segment
constexpr int SEGOFF = N_COLS / 2;          // 4096: segment B offset
constexpr int CHUNK  = (TPB / 32) * WTOK;   // 2048 tokens/CTA/segment
constexpr float SENT = -60000.0f;           // fp16-exact sentinel
constexpr float NEGV = -1.0e9f;
constexpr unsigned FULL = 0xffffffffu;
}

__device__ __forceinline__ unsigned h2u(__half2 v) { return *reinterpret_cast<unsigned*>(&v); }
__device__ __forceinline__ __half2 u2h(unsigned u) { return *reinterpret_cast<__half2*>(&u); }

__global__ __launch_bounds__(TPB, 6) void span_boost_kernel(
    const float* __restrict__ scores,
    const int*   __restrict__ mask,
    const float* __restrict__ gamma_p,
    const float* __restrict__ wlog,
    float*       __restrict__ out)
{
    const float NINF = __int_as_float(0xff800000);
    const int tid  = threadIdx.x;
    const int lane = tid & 31;
    const int wid  = tid >> 5;
    const int row  = blockIdx.y;
    const float* srow = scores + (size_t)row * N_COLS;
    const int*   mrow = mask   + (size_t)row * N_COLS;

    const int wb = blockIdx.x * CHUNK + wid * WTOK;  // warp base (segment A)
    const int t0 = wb + lane * K_TOK;                // lane base (segment A)

    // ---- lane-parallel softmax: wwf[j] = weight of width j+2 (fp32) ----
    float wwf[NW];
    float cfix;                            // exact sentinel-class boost value
    {
        float lg = (lane < W_MAX) ? __ldg(wlog + lane) : NINF;
        float mx = lg;
        #pragma unroll
        for (int o = 16; o >= 1; o >>= 1)
            mx = fmaxf(mx, __shfl_xor_sync(FULL, mx, o));
        float e = (lane < W_MAX) ? __expf(lg - mx) : 0.f;
        float s = e;
        #pragma unroll
        for (int o = 16; o >= 1; o >>= 1)
            s += __shfl_xor_sync(FULL, s, o);
        float wwv = __fdividef(e, s);
        float wv = (lane >= 1 && lane <= 14) ? wwv : 1.0f;
        #pragma unroll
        for (int o = 16; o >= 1; o >>= 1)
            wv = fminf(wv, __shfl_xor_sync(FULL, wv, o));
        cfix = NEGV * wv;
        #pragma unroll
        for (int j = 0; j < NW; j++)
            wwf[j] = __shfl_sync(FULL, wwv, j + 1);
    }

    // ---- warp-left halo, BOTH segments in parallel (fp32, atomics-free) ----
    float acc = NINF;                      // halo boost for warp token l (per group)
    {
        const int l   = lane & 15;
        const bool act = (l < HALO);
        const int hb  = wb + ((lane >= 16) ? SEGOFF : 0);
        float hv[W_MAX];
        #pragma unroll
        for (int k = 0; k < W_MAX; k++) {
            int g = hb - HALO + l + k;
            float v = SENT;
            if (act && g >= 0) v = (mrow[g] == 0) ? SENT : srow[g];
            hv[k] = v;
        }
        float hw[NW];
        float m = fminf(hv[0], hv[1]);
        hw[0] = wwf[0] * m;
        #pragma unroll
        for (int w = 3; w <= W_MAX; w++) {
            m = fminf(m, hv[w - 1]);
            hw[w - 2] = wwf[w - 2] * m;
        }
        float Gv[16];                      // Gv[d] = max_{w>=d} hw
        Gv[15] = hw[13];
        #pragma unroll
        for (int d = 14; d >= 2; d--) Gv[d] = fmaxf(Gv[d + 1], hw[d - 2]);
        Gv[1] = Gv[2];
        #pragma unroll
        for (int k = 0; k < HALO; k++) {   // token l <- start l+k, depth 15-k
            float v = __shfl_down_sync(FULL, Gv[15 - k], k);
            if (act && l + k < HALO) acc = fmaxf(acc, v);
        }
    }

    // ---- packed masked values r[0..15] = {segA, segB} tokens ----
    __half2 r[30];
    #pragma unroll
    for (int q = 0; q < 4; q++) {
        int ga = t0 + 4 * q, gb = ga + SEGOFF;
        float4 sa = *reinterpret_cast<const float4*>(srow + ga);
        int4   ma = *reinterpret_cast<const int4*>(mrow + ga);
        float4 sb = *reinterpret_cast<const float4*>(srow + gb);
        int4   mb = *reinterpret_cast<const int4*>(mrow + gb);
        r[4*q+0] = __floats2half2_rn(ma.x == 0 ? SENT : sa.x, mb.x == 0 ? SENT : sb.x);
        r[4*q+1] = __floats2half2_rn(ma.y == 0 ? SENT : sa.y, mb.y == 0 ? SENT : sb.y);
        r[4*q+2] = __floats2half2_rn(ma.z == 0 ? SENT : sa.z, mb.z == 0 ? SENT : sb.z);
        r[4*q+3] = __floats2half2_rn(ma.w == 0 ? SENT : sa.w, mb.w == 0 ? SENT : sb.w);
    }
    // right halo r[16..29]: lane+1's r[0..13] (both halves at once)
    #pragma unroll
    for (int k = 0; k < HALO; k++)
        r[16 + k] = u2h(__shfl_down_sync(FULL, h2u(r[k]), 1));
    if (lane == 31) {                      // real right halo at warp boundary
        #pragma unroll
        for (int q = 0; q < 4; q++) {
            int ga = t0 + 16 + 4 * q, gb = ga + SEGOFF;
            float va[4] = {SENT, SENT, SENT, SENT};
            float vb[4] = {SENT, SENT, SENT, SENT};
            if (ga + 3 < N_COLS) {
                float4 s4 = *reinterpret_cast<const float4*>(srow + ga);
                int4   m4 = *reinterpret_cast<const int4*>(mrow + ga);
                va[0] = m4.x == 0 ? SENT : s4.x; va[1] = m4.y == 0 ? SENT : s4.y;
                va[2] = m4.z == 0 ? SENT : s4.z; va[3] = m4.w == 0 ? SENT : s4.w;
            }
            if (gb + 3 < N_COLS) {
                float4 s4 = *reinterpret_cast<const float4*>(srow + gb);
                int4   m4 = *reinterpret_cast<const int4*>(mrow + gb);
                vb[0] = m4.x == 0 ? SENT : s4.x; vb[1] = m4.y == 0 ? SENT : s4.y;
                vb[2] = m4.z == 0 ? SENT : s4.z; vb[3] = m4.w == 0 ? SENT : s4.w;
            }
            #pragma unroll
            for (int c = 0; c < 4; c++) {
                int idx = 16 + 4 * q + c;
                if (idx < 30) r[idx] = __floats2half2_rn(va[c], vb[c]);
            }
        }
    }

    // ---- packed weights (wwf dies here) ----
    __half2 ww2[NW];
    #pragma unroll
    for (int j = 0; j < NW; j++) ww2[j] = __float2half2_rn(wwf[j]);
    const __half2 SENT2 = __float2half2_rn(SENT);

    // ---- M prologue: M[w] = m_w(start 16) = min(r[16..15+w]), w = 1..14 ----
    // (r[16..29] is consumed here and dies -> lower live set in main loop)
    __half2 M[16];                         // index 1..15 used
    M[1] = r[16];
    #pragma unroll
    for (int w = 2; w <= 14; w++) M[w] = __hmin2(M[w - 1], r[15 + w]);

    // ---- 16 packed starts, descending; van-Herk recursion:
    //      m_w(j) = min(r[j], m_{w-1}(j+1)) -> all 14 mins depth-1/iter. ----
    __half2 boost[K_TOK + HALO];
    #pragma unroll
    for (int jj = 0; jj < K_TOK; jj++) {
        const int j = K_TOK - 1 - jj;      // 15 .. 0
        const __half2 rj = r[j];
        // in-place descending-w update reads old M[w-1]: all independent
        #pragma unroll
        for (int w = W_MAX; w >= 2; w--) M[w] = __hmin2(rj, M[w - 1]);
        M[1] = rj;

        __half2 g = __hmul2(M[W_MAX], ww2[NW - 1]);         // d = 15
        if (j == K_TOK - 1) boost[j + 14] = g;
        else                boost[j + 14] = __hmax2(boost[j + 14], g);
        #pragma unroll
        for (int d = W_MAX - 1; d >= 2; d--) {              // d = 14..2
            g = __hmax2(g, __hmul2(M[d], ww2[d - 2]));
            if (j == K_TOK - 1) boost[j + d - 1] = g;
            else                boost[j + d - 1] = __hmax2(boost[j + d - 1], g);
        }
        if (j >= K_TOK - 2) boost[j] = g;                   // d = 1: first touch
        else                boost[j] = __hmax2(boost[j], g);
        if (j >= 2) {                                       // handoff slot j-2
            unsigned tin = __shfl_up_sync(FULL, h2u(boost[j + 14]), 1);
            boost[j - 2] = (lane == 0) ? SENT2 : u2h(tin);
        }
    }

    // ---- fold halo boosts into lane 0's slots 0..13 (both halves) ----
    #pragma unroll
    for (int i = 0; i < HALO; i++) {
        float vA = __shfl_sync(FULL, acc, i);
        float vB = __shfl_sync(FULL, acc, 16 + i);
        if (lane == 0)
            boost[i] = __hmax2(boost[i], __floats2half2_rn(vA, vB));
    }

    // ---- epilogue: sentinel fixup + max(boost, masked) + axpy (fp32) ----
    const float gamma = *gamma_p;
    float* orow = out + (size_t)row * N_COLS;
    #pragma unroll
    for (int q = 0; q < 4; q++) {
        int ga = t0 + 4 * q, gb = ga + SEGOFF;
        float4 sa = *reinterpret_cast<const float4*>(srow + ga);
        float4 sb = *reinterpret_cast<const float4*>(srow + gb);
        float4 oa, ob;
        #pragma unroll
        for (int c = 0; c < 4; c++) {
            int k = 4 * q + c;
            float bl = __low2float(boost[k]);
            float bh = __high2float(boost[k]);
            bl = (bl > -1000.f) ? bl : cfix;   // sentinel-class -> exact value
            bh = (bh > -1000.f) ? bh : cfix;
            float rl = __low2float(r[k]);
            float rh = __high2float(r[k]);
            float sA = (&sa.x)[c], sB = (&sb.x)[c];
            float fl = (rl == SENT) ? bl : fmaxf(bl, sA);
            float fh = (rh == SENT) ? bh : fmaxf(bh, sB);
            (&oa.x)[c] = sA + gamma * fl;
            (&ob.x)[c] = sB + gamma * fh;
        }
        *reinterpret_cast<float4*>(&orow[ga]) = oa;
        *reinterpret_cast<float4*>(&orow[gb]) = ob;
    }
}

extern "C" void kernel_launch(void* const* d_in, const int* in_sizes, int n_in,
                              void* d_out, int out_size)
{
    const float* scores = (const float*)d_in[0];
    const int*   mask   = (const int*)d_in[1];
    const float* gamma  = (const float*)d_in[2];
    const float* wlog   = (const float*)d_in[3];
    float* out = (float*)d_out;
    const int B = in_sizes[0] / N_COLS;   // 512
    dim3 grid(SEGOFF / CHUNK, B);         // (2, 512)
    span_boost_kernel<<<grid, TPB>>>(scores, mask, gamma, wlog, out);
}

// round 15
// speedup vs baseline: 1.0573x; 1.0573x over previous
#include <cuda_runtime.h>
#include <cuda_fp16.h>

namespace {
constexpr int N_COLS = 8192;
constexpr int W_MAX  = 15;     // widths w = 2..15
constexpr int NW     = 14;
constexpr int HALO   = 14;     // W_MAX - 1
constexpr int TPB    = 128;    // 4 warps
constexpr int K_TOK  = 16;     // tokens per lane PER SEGMENT
constexpr int WTOK   = 32 * K_TOK;          // 512 tokens/warp/segment
constexpr int SEGOFF = N_COLS / 2;          // 4096: segment B offset
constexpr int CHUNK  = (TPB / 32) * WTOK;   // 2048 tokens/CTA/segment
constexpr float SENT = -60000.0f;           // fp16-exact sentinel
constexpr float NEGV = -1.0e9f;
constexpr unsigned FULL = 0xffffffffu;
}

__device__ __forceinline__ unsigned h2u(__half2 v) { return *reinterpret_cast<unsigned*>(&v); }
__device__ __forceinline__ __half2 u2h(unsigned u) { return *reinterpret_cast<__half2*>(&u); }

__global__ __launch_bounds__(TPB, 5) void span_boost_kernel(
    const float* __restrict__ scores,
    const int*   __restrict__ mask,
    const float* __restrict__ gamma_p,
    const float* __restrict__ wlog,
    float*       __restrict__ out)
{
    const float NINF = __int_as_float(0xff800000);
    const int tid  = threadIdx.x;
    const int lane = tid & 31;
    const int wid  = tid >> 5;
    const int row  = blockIdx.y;
    const float* srow = scores + (size_t)row * N_COLS;
    const int*   mrow = mask   + (size_t)row * N_COLS;

    const int wb = blockIdx.x * CHUNK + wid * WTOK;  // warp base (segment A)
    const int t0 = wb + lane * K_TOK;                // lane base (segment A)

    // ---- lane-parallel softmax: wwf[j] = weight of width j+2 (fp32) ----
    float wwf[NW];
    float cfix;                            // exact sentinel-class boost value
    {
        float lg = (lane < W_MAX) ? __ldg(wlog + lane) : NINF;
        float mx = lg;
        #pragma unroll
        for (int o = 16; o >= 1; o >>= 1)
            mx = fmaxf(mx, __shfl_xor_sync(FULL, mx, o));
        float e = (lane < W_MAX) ? __expf(lg - mx) : 0.f;
        float s = e;
        #pragma unroll
        for (int o = 16; o >= 1; o >>= 1)
            s += __shfl_xor_sync(FULL, s, o);
        float wwv = __fdividef(e, s);
        float wv = (lane >= 1 && lane <= 14) ? wwv : 1.0f;
        #pragma unroll
        for (int o = 16; o >= 1; o >>= 1)
            wv = fminf(wv, __shfl_xor_sync(FULL, wv, o));
        cfix = NEGV * wv;
        #pragma unroll
        for (int j = 0; j < NW; j++)
            wwf[j] = __shfl_sync(FULL, wwv, j + 1);
    }

    // ---- warp-left halo, BOTH segments in parallel (fp32, atomics-free) ----
    float acc = NINF;                      // halo boost for warp token l (per group)
    {
        const int l   = lane & 15;
        const bool act = (l < HALO);
        const int hb  = wb + ((lane >= 16) ? SEGOFF : 0);
        float hv[W_MAX];
        #pragma unroll
        for (int k = 0; k < W_MAX; k++) {
            int g = hb - HALO + l + k;
            float v = SENT;
            if (act && g >= 0) v = (mrow[g] == 0) ? SENT : srow[g];
            hv[k] = v;
        }
        float hw[NW];
        float m = fminf(hv[0], hv[1]);
        hw[0] = wwf[0] * m;
        #pragma unroll
        for (int w = 3; w <= W_MAX; w++) {
            m = fminf(m, hv[w - 1]);
            hw[w - 2] = wwf[w - 2] * m;
        }
        float Gv[16];                      // Gv[d] = max_{w>=d} hw
        Gv[15] = hw[13];
        #pragma unroll
        for (int d = 14; d >= 2; d--) Gv[d] = fmaxf(Gv[d + 1], hw[d - 2]);
        Gv[1] = Gv[2];
        #pragma unroll
        for (int k = 0; k < HALO; k++) {   // token l <- start l+k, depth 15-k
            float v = __shfl_down_sync(FULL, Gv[15 - k], k);
            if (act && l + k < HALO) acc = fmaxf(acc, v);
        }
    }

    // ---- packed masked values r[0..15] = {segA, segB} tokens ----
    __half2 r[30];
    #pragma unroll
    for (int q = 0; q < 4; q++) {
        int ga = t0 + 4 * q, gb = ga + SEGOFF;
        float4 sa = *reinterpret_cast<const float4*>(srow + ga);
        int4   ma = *reinterpret_cast<const int4*>(mrow + ga);
        float4 sb = *reinterpret_cast<const float4*>(srow + gb);
        int4   mb = *reinterpret_cast<const int4*>(mrow + gb);
        r[4*q+0] = __floats2half2_rn(ma.x == 0 ? SENT : sa.x, mb.x == 0 ? SENT : sb.x);
        r[4*q+1] = __floats2half2_rn(ma.y == 0 ? SENT : sa.y, mb.y == 0 ? SENT : sb.y);
        r[4*q+2] = __floats2half2_rn(ma.z == 0 ? SENT : sa.z, mb.z == 0 ? SENT : sb.z);
        r[4*q+3] = __floats2half2_rn(ma.w == 0 ? SENT : sa.w, mb.w == 0 ? SENT : sb.w);
    }
    // right halo r[16..29]: lane+1's r[0..13] (both halves at once)
    #pragma unroll
    for (int k = 0; k < HALO; k++)
        r[16 + k] = u2h(__shfl_down_sync(FULL, h2u(r[k]), 1));
    if (lane == 31) {                      // real right halo at warp boundary
        #pragma unroll
        for (int q = 0; q < 4; q++) {
            int ga = t0 + 16 + 4 * q, gb = ga + SEGOFF;
            float va[4] = {SENT, SENT, SENT, SENT};
            float vb[4] = {SENT, SENT, SENT, SENT};
            if (ga + 3 < N_COLS) {
                float4 s4 = *reinterpret_cast<const float4*>(srow + ga);
                int4   m4 = *reinterpret_cast<const int4*>(mrow + ga);
                va[0] = m4.x == 0 ? SENT : s4.x; va[1] = m4.y == 0 ? SENT : s4.y;
                va[2] = m4.z == 0 ? SENT : s4.z; va[3] = m4.w == 0 ? SENT : s4.w;
            }
            if (gb + 3 < N_COLS) {
                float4 s4 = *reinterpret_cast<const float4*>(srow + gb);
                int4   m4 = *reinterpret_cast<const int4*>(mrow + gb);
                vb[0] = m4.x == 0 ? SENT : s4.x; vb[1] = m4.y == 0 ? SENT : s4.y;
                vb[2] = m4.z == 0 ? SENT : s4.z; vb[3] = m4.w == 0 ? SENT : s4.w;
            }
            #pragma unroll
            for (int c = 0; c < 4; c++) {
                int idx = 16 + 4 * q + c;
                if (idx < 30) r[idx] = __floats2half2_rn(va[c], vb[c]);
            }
        }
    }

    // ---- packed weights (wwf dies here) ----
    __half2 ww2[NW];
    #pragma unroll
    for (int j = 0; j < NW; j++) ww2[j] = __float2half2_rn(wwf[j]);
    const __half2 SENT2 = __float2half2_rn(SENT);

    // ---- M prologue: M[w] = m_w(start 16) = min(r[16..15+w]), w = 1..14 ----
    __half2 M[16];                         // index 1..15 used
    M[1] = r[16];
    #pragma unroll
    for (int w = 2; w <= 14; w++) M[w] = __hmin2(M[w - 1], r[15 + w]);

    // ---- 16 packed starts, descending; van-Herk recursion:
    //      m_w(j) = min(r[j], m_{w-1}(j+1)) -> all 14 mins depth-1/iter. ----
    __half2 boost[K_TOK + HALO];
    #pragma unroll
    for (int jj = 0; jj < K_TOK; jj++) {
        const int j = K_TOK - 1 - jj;      // 15 .. 0
        const __half2 rj = r[j];
        #pragma unroll
        for (int w = W_MAX; w >= 2; w--) M[w] = __hmin2(rj, M[w - 1]);
        M[1] = rj;

        __half2 g = __hmul2(M[W_MAX], ww2[NW - 1]);         // d = 15
        if (j == K_TOK - 1) boost[j + 14] = g;
        else                boost[j + 14] = __hmax2(boost[j + 14], g);
        #pragma unroll
        for (int d = W_MAX - 1; d >= 2; d--) {              // d = 14..2
            g = __hmax2(g, __hmul2(M[d], ww2[d - 2]));
            if (j == K_TOK - 1) boost[j + d - 1] = g;
            else                boost[j + d - 1] = __hmax2(boost[j + d - 1], g);
        }
        if (j >= K_TOK - 2) boost[j] = g;                   // d = 1: first touch
        else                boost[j] = __hmax2(boost[j], g);
        if (j >= 2) {                                       // handoff slot j-2
            unsigned tin = __shfl_up_sync(FULL, h2u(boost[j + 14]), 1);
            boost[j - 2] = (lane == 0) ? SENT2 : u2h(tin);
        }
    }

    // ---- fold halo boosts into lane 0's slots 0..13 (both halves) ----
    #pragma unroll
    for (int i = 0; i < HALO; i++) {
        float vA = __shfl_sync(FULL, acc, i);
        float vB = __shfl_sync(FULL, acc, 16 + i);
        if (lane == 0)
            boost[i] = __hmax2(boost[i], __floats2half2_rn(vA, vB));
    }

    // ---- epilogue: sentinel fixup + max(boost, masked) + axpy (fp32) ----
    const float gamma = *gamma_p;
    float* orow = out + (size_t)row * N_COLS;
    #pragma unroll
    for (int q = 0; q < 4; q++) {
        int ga = t0 + 4 * q, gb = ga + SEGOFF;
        float4 sa = *reinterpret_cast<const float4*>(srow + ga);
        float4 sb = *reinterpret_cast<const float4*>(srow + gb);
        float4 oa, ob;
        #pragma unroll
        for (int c = 0; c < 4; c++) {
            int k = 4 * q + c;
            float bl = __low2float(boost[k]);
            float bh = __high2float(boost[k]);
            bl = (bl > -1000.f) ? bl : cfix;   // sentinel-class -> exact value
            bh = (bh > -1000.f) ? bh : cfix;
            float rl = __low2float(r[k]);
            float rh = __high2float(r[k]);
            float sA = (&sa.x)[c], sB = (&sb.x)[c];
            float fl = (rl == SENT) ? bl : fmaxf(bl, sA);
            float fh = (rh == SENT) ? bh : fmaxf(bh, sB);
            (&oa.x)[c] = sA + gamma * fl;
            (&ob.x)[c] = sB + gamma * fh;
        }
        *reinterpret_cast<float4*>(&orow[ga]) = oa;
        *reinterpret_cast<float4*>(&orow[gb]) = ob;
    }
}

extern "C" void kernel_launch(void* const* d_in, const int* in_sizes, int n_in,
                              void* d_out, int out_size)
{
    const float* scores = (const float*)d_in[0];
    const int*   mask   = (const int*)d_in[1];
    const float* gamma  = (const float*)d_in[2];
    const float* wlog   = (const float*)d_in[3];
    float* out = (float*)d_out;
    const int B = in_sizes[0] / N_COLS;   // 512
    dim3 grid(SEGOFF / CHUNK, B);         // (2, 512)
    span_boost_kernel<<<grid, TPB>>>(scores, mask, gamma, wlog, out);
}